// round 6
// baseline (speedup 1.0000x reference)
#include <cuda_runtime.h>
#include <cstdint>

// Problem constants: N=500000, D=64, K=256
#define KC   256
#define DC   64
#define TM   128
#define NREP 8

// Scratch device globals (BSS zero; finalize re-zeroes after consuming)
__device__ float4 g_segsum4[NREP][KC * DC / 4];
__device__ int    g_segcnt[NREP][KC];
__device__ float  g_losssum;

// ---- dynamic SMEM layout (bytes) ----
#define C2_OFF    0                       // 256 f32
#define X2_OFF    1024                    // 128 f32
#define EB_OFF    1536                    // 128 f32
#define EI_OFF    2048                    // 128 int
#define MX_OFF    2560                    // 1 int
#define XB_OFF    4096                    // 128 x 144B bf16 x rows
#define XB_STRIDE 144
#define CB_OFF    (XB_OFF + TM * 144)     // 256 x 144B bf16 center rows
#define CB_STRIDE 144
#define CM_OFF    (CB_OFF + KC * 144)     // 128 x 264B u8 dist rows
#define CM_STRIDE 264
#define SMEM_TOTAL (CM_OFF + TM * 264)    // 93184 -> 2 CTAs/SM

// ---------------- helpers ----------------
__device__ __forceinline__ uint32_t smem_u32(const void* p) {
    uint32_t a;
    asm("{ .reg .u64 t; cvta.to.shared.u64 t, %1; cvt.u32.u64 %0, t; }"
        : "=r"(a) : "l"(p));
    return a;
}
__device__ __forceinline__ uint32_t lds32(uint32_t a) {
    uint32_t v; asm volatile("ld.shared.b32 %0, [%1];" : "=r"(v) : "r"(a));
    return v;
}
__device__ __forceinline__ void sts64(uint32_t a, uint64_t v) {
    asm volatile("st.shared.b64 [%0], %1;" :: "r"(a), "l"(v) : "memory");
}
__device__ __forceinline__ void sts16(uint32_t a, uint16_t v) {
    asm volatile("st.shared.u16 [%0], %1;" :: "r"(a), "h"(v) : "memory");
}
__device__ __forceinline__ uint32_t cvt_bf16x2(float lo, float hi) {
    uint32_t r;
    asm("cvt.rn.bf16x2.f32 %0, %1, %2;" : "=r"(r) : "f"(hi), "f"(lo));
    return r;
}
__device__ __forceinline__ void red_add_v4(float4* a, float x, float y,
                                           float z, float w) {
    asm volatile("red.global.add.v4.f32 [%0], {%1,%2,%3,%4};"
                 :: "l"(a), "f"(x), "f"(y), "f"(z), "f"(w) : "memory");
}
__device__ __forceinline__ void mma_bf16(float& d0, float& d1, float& d2, float& d3,
                                         const uint32_t* a, uint32_t b0, uint32_t b1) {
    asm volatile(
        "mma.sync.aligned.m16n8k16.row.col.f32.bf16.bf16.f32 "
        "{%0,%1,%2,%3}, {%4,%5,%6,%7}, {%8,%9}, {%0,%1,%2,%3};"
        : "+f"(d0), "+f"(d1), "+f"(d2), "+f"(d3)
        : "r"(a[0]), "r"(a[1]), "r"(a[2]), "r"(a[3]), "r"(b0), "r"(b1));
}
__device__ __forceinline__ int quant(float t) {
    int q = __float2int_rd(t + 128.0f);
    return max(0, min(255, q));
}

// ---------------------------------------------------------------------------
// MAIN: 128-point tile/CTA, 4 warps. ONE bf16 HMMA pass -> u8 dist cache in
// smem -> warp-cooperative exact fp32 refine of ~2 candidates/row.
// ---------------------------------------------------------------------------
__global__ __launch_bounds__(128) void dcn_main_kernel(
    const float* __restrict__ emb,
    const float* __restrict__ centers,
    float* __restrict__ out_labels,
    int n)
{
    extern __shared__ char smem[];
    const uint32_t sb = smem_u32(smem);
    float* c2s = (float*)(smem + C2_OFF);
    float* x2s = (float*)(smem + X2_OFF);
    float* ebs = (float*)(smem + EB_OFF);
    int*   eis = (int*)(smem + EI_OFF);
    int*   mxp = (int*)(smem + MX_OFF);

    const int tid  = threadIdx.x;
    const int warp = tid >> 5, lane = tid & 31;
    const int g = lane >> 2, c = lane & 3;
    const int base = blockIdx.x * TM;
    const int npts = min(TM, n - base);
    const float4* cen4 = (const float4*)centers;
    const unsigned FULL = 0xffffffffu;

    // phase -1: zero reduction cells
    x2s[tid] = 0.0f;
    if (tid == 0) *mxp = 0;
    __syncthreads();

    // --- phase 0a: x -> bf16 tile + x2 (shared atomics), coalesced ---
    const float4* emb4 = (const float4*)emb + (size_t)base * (DC / 4);
#pragma unroll
    for (int i = 0; i < 16; i++) {
        int f = tid + i * 128;
        int row = f >> 4, c4 = f & 15;
        float4 v = make_float4(0.f, 0.f, 0.f, 0.f);
        if (row < npts) {
            v = emb4[f];
            float ps = fmaf(v.x, v.x, v.y * v.y) + fmaf(v.z, v.z, v.w * v.w);
            atomicAdd(&x2s[row], ps);
        }
        uint64_t pk = (uint64_t)cvt_bf16x2(v.x, v.y)
                    | ((uint64_t)cvt_bf16x2(v.z, v.w) << 32);
        sts64(sb + XB_OFF + row * XB_STRIDE + c4 * 8, pk);
    }
    // --- phase 0b: centers -> bf16 tile + exact c2 + maxc2 (one global read) ---
    for (int k = tid; k < KC; k += 128) {
        const float4* cr = cen4 + k * (DC / 4);
        float acc = 0.f;
#pragma unroll
        for (int q = 0; q < DC / 4; q++) {
            float4 v = __ldg(cr + q);
            acc = fmaf(v.x, v.x, acc); acc = fmaf(v.y, v.y, acc);
            acc = fmaf(v.z, v.z, acc); acc = fmaf(v.w, v.w, acc);
            uint64_t pk = (uint64_t)cvt_bf16x2(v.x, v.y)
                        | ((uint64_t)cvt_bf16x2(v.z, v.w) << 32);
            sts64(sb + CB_OFF + k * CB_STRIDE + q * 8, pk);
        }
        c2s[k] = acc;
        atomicMax(mxp, __float_as_int(acc));   // positive floats: int-monotonic
    }
    __syncthreads();

    // --- A fragments ---
    uint32_t af[2][4][4];
#pragma unroll
    for (int m = 0; m < 2; m++)
#pragma unroll
        for (int s = 0; s < 4; s++) {
            uint32_t r0 = warp * 32 + m * 16 + g;
            uint32_t a = sb + XB_OFF + r0 * XB_STRIDE + (s * 16 + c * 2) * 2;
            af[m][s][0] = lds32(a);
            af[m][s][1] = lds32(a + 8 * XB_STRIDE);
            af[m][s][2] = lds32(a + 16);
            af[m][s][3] = lds32(a + 8 * XB_STRIDE + 16);
        }
    const int rows[4] = { warp * 32 + g,      warp * 32 + g + 8,
                          warp * 32 + g + 16, warp * 32 + g + 24 };

    // ===== Pass A: single GEMM, quantize dists to u8 cache =====
#pragma unroll 1
    for (int ch = 0; ch < 32; ch++) {
        uint32_t b0[4], b1[4];
        uint32_t ba = sb + CB_OFF + (ch * 8 + g) * CB_STRIDE + c * 4;
#pragma unroll
        for (int s = 0; s < 4; s++) {
            b0[s] = lds32(ba + s * 32);
            b1[s] = lds32(ba + s * 32 + 16);
        }
        int k0 = ch * 8 + c * 2;
        float cc0 = c2s[k0], cc1 = c2s[k0 + 1];
#pragma unroll
        for (int m = 0; m < 2; m++) {
            float d0 = 0.f, d1 = 0.f, d2 = 0.f, d3 = 0.f;
#pragma unroll
            for (int s = 0; s < 4; s++)
                mma_bf16(d0, d1, d2, d3, af[m][s], b0[s], b1[s]);
            int q0 = quant(fmaf(-2.f, d0, cc0));
            int q1 = quant(fmaf(-2.f, d1, cc1));
            int q2 = quant(fmaf(-2.f, d2, cc0));
            int q3 = quant(fmaf(-2.f, d3, cc1));
            sts16(sb + CM_OFF + rows[2 * m] * CM_STRIDE + ch * 8 + c * 2,
                  (uint16_t)(q0 | (q1 << 8)));
            sts16(sb + CM_OFF + rows[2 * m + 1] * CM_STRIDE + ch * 8 + c * 2,
                  (uint16_t)(q2 | (q3 << 8)));
        }
    }
    __syncwarp();

    // ===== Phase B: warp-cooperative exact refine, one row at a time =====
    const float cmax = sqrtf(__int_as_float(*mxp));
#pragma unroll 1
    for (int i = 0; i < 32; i++) {
        int r = warp * 32 + i;
        float2 xrow = make_float2(0.f, 0.f);
        if (r < npts)
            xrow = __ldg((const float2*)(emb + (size_t)(base + r) * DC) + lane);

        uint32_t w0 = lds32(sb + CM_OFF + r * CM_STRIDE + lane * 8);
        uint32_t w1 = lds32(sb + CM_OFF + r * CM_STRIDE + lane * 8 + 4);
        unsigned mn = __vminu4(w0, w1);
#pragma unroll
        for (int o = 16; o; o >>= 1)
            mn = __vminu4(mn, __shfl_xor_sync(FULL, mn, o));
        mn = __vminu4(mn, mn >> 16);
        mn = __vminu4(mn, mn >> 8);
        int gq = (int)(mn & 0xFF);

        float win = sqrtf(x2s[r]) * cmax * 0.025f;   // >= rigorous bf16 bound
        int TQ = min(gq + 1 + (int)ceilf(win), 255);
        unsigned tq4 = (unsigned)TQ * 0x01010101u;
        unsigned m0 = __vcmpleu4(w0, tq4) & 0x01010101u;
        unsigned m1 = __vcmpleu4(w1, tq4) & 0x01010101u;
        unsigned cand = ((m0 * 0x01020408u) >> 24)
                      | (((m1 * 0x01020408u) >> 24) << 4);
        unsigned ball = __ballot_sync(FULL, cand != 0);

        float eb = 3.4e38f; int ei = 0;
        while (ball) {
            int L = __ffs(ball) - 1; ball &= ball - 1;
            unsigned cm = __shfl_sync(FULL, cand, L);
            while (cm) {
                int b = __ffs(cm) - 1; cm &= cm - 1;
                int k = L * 8 + b;
                float2 cf = __ldg((const float2*)(centers + k * DC) + lane);
                float p = fmaf(xrow.x, cf.x, xrow.y * cf.y);
#pragma unroll
                for (int o = 16; o; o >>= 1)
                    p += __shfl_xor_sync(FULL, p, o);
                float de = fmaf(-2.0f, p, c2s[k]);
                if (de < eb) { eb = de; ei = k; }   // ascending k: first-min
            }
        }
        if (lane == 0) { ebs[r] = eb; eis[r] = ei; }
    }
    __syncwarp();

    // ===== Phase C: outputs + segment sums + loss (thread = row) =====
    float lossval = 0.0f;
    if (tid < npts) {
        int row = tid;
        int lab = eis[row];
        out_labels[base + row] = (float)lab;
        lossval = x2s[row] + ebs[row];

        int rep = (blockIdx.x ^ warp) & (NREP - 1);
        float4* dst = g_segsum4[rep] + lab * (DC / 4);
        const float4* xr = (const float4*)(emb + (size_t)(base + row) * DC);
#pragma unroll
        for (int q = 0; q < 16; q++) {
            int qq = (q + lane) & 15;
            float4 v = __ldg(xr + qq);
            red_add_v4(dst + qq, v.x, v.y, v.z, v.w);
        }
        atomicAdd(&g_segcnt[rep][lab], 1);
    }
#pragma unroll
    for (int off = 16; off; off >>= 1)
        lossval += __shfl_down_sync(FULL, lossval, off);
    if (lane == 0 && lossval != 0.0f) atomicAdd(&g_losssum, lossval);
}

// ---------------------------------------------------------------------------
// FINALIZE + RE-ZERO. Output: [labels N][loss 1][centers K*D][counts K] (f32)
// ---------------------------------------------------------------------------
__global__ void dcn_finalize_kernel(const float* __restrict__ centers,
                                    const int*   __restrict__ counts,
                                    float* __restrict__ out,
                                    int n)
{
    int k = blockIdx.x;
    int d = threadIdx.x;
    int idx = k * DC + d;

    float s = 0.0f;
#pragma unroll
    for (int r = 0; r < NREP; r++) {
        float* p = (float*)g_segsum4[r] + idx;
        s += *p;
        *p = 0.0f;
    }
    int cnt = 0;
#pragma unroll
    for (int r = 0; r < NREP; r++) cnt += g_segcnt[r][k];
    __syncthreads();
    if (d == 0) {
#pragma unroll
        for (int r = 0; r < NREP; r++) g_segcnt[r][k] = 0;
    }
    float oldw = (float)counts[k];
    float neww = oldw + (float)cnt;
    out[n + 1 + idx] = fmaf(oldw, centers[idx], s) / neww;
    if (d == 0) out[n + 1 + KC * DC + k] = neww;
    if (k == 0 && d == 0) {
        out[n] = g_losssum / (float)n;
        g_losssum = 0.0f;
    }
}

// ---------------------------------------------------------------------------
extern "C" void kernel_launch(void* const* d_in, const int* in_sizes, int n_in,
                              void* d_out, int out_size)
{
    const float* emb     = (const float*)d_in[0];
    const float* centers = (const float*)d_in[1];
    const int*   counts  = (const int*)d_in[2];
    float* out = (float*)d_out;

    int n = in_sizes[0] / DC;
    int nblk = (n + TM - 1) / TM;

    cudaFuncSetAttribute(dcn_main_kernel,
                         cudaFuncAttributeMaxDynamicSharedMemorySize, SMEM_TOTAL);

    dcn_main_kernel<<<nblk, TM, SMEM_TOTAL>>>(emb, centers, out, n);
    dcn_finalize_kernel<<<KC, DC>>>(centers, counts, out, n);
}